// round 9
// baseline (speedup 1.0000x reference)
#include <cuda_runtime.h>
#include <cstdint>

#define N_NODES 8192
#define DIM 256
#define SPLIT 2
#define KSPAN (N_NODES / SPLIT)   // 4096
#define BK 32
#define NCH (KSPAN / BK)          // 128 iters per CTA
#define BM 64
#define NCHUNK_TOT (N_NODES / BK) // 256 packed V chunks
#define NWORDS (N_NODES / 32)     // 256 bitmask words per row
#define LOG2E 1.4426950408889634f

// ---- device scratch (static only) ----
__device__ float    g_Wh[N_NODES * DIM];
__device__ float2   g_Vp[NCHUNK_TOT * 16 * 256];   // packed tf32 V pairs (8 MB)
__device__ uint32_t g_abT[NWORDS * N_NODES];       // bit-packed adj, transposed [w][i]
__device__ float    g_h1[N_NODES * DIM];
__device__ float    g_Dp[SPLIT][N_NODES * DIM];
__device__ float    g_Zp[SPLIT][N_NODES];
__device__ float    g_sL[N_NODES];                 // s * log2(e)
__device__ float    g_dL[N_NODES];                 // d * log2(e)

__device__ __forceinline__ float tf32r(float x) {
    uint32_t u;
    asm("cvt.rna.tf32.f32 %0, %1;" : "=r"(u) : "f"(x));
    return __uint_as_float(u);
}
__device__ __forceinline__ float ex2(float x) {
    float r;
    asm("ex2.approx.f32 %0, %1;" : "=f"(r) : "f"(x));
    return r;
}
__device__ __forceinline__ void mma_tf32(float4& c, const uint32_t a[4],
                                         uint32_t b0, uint32_t b1) {
    asm volatile(
        "mma.sync.aligned.m16n8k8.row.col.f32.tf32.tf32.f32 "
        "{%0,%1,%2,%3}, {%4,%5,%6,%7}, {%8,%9}, {%0,%1,%2,%3};"
        : "+f"(c.x), "+f"(c.y), "+f"(c.z), "+f"(c.w)
        : "r"(a[0]), "r"(a[1]), "r"(a[2]), "r"(a[3]), "r"(b0), "r"(b1));
}
__device__ __forceinline__ void cp_async16(uint32_t dst, const void* src) {
    asm volatile("cp.async.cg.shared.global [%0], [%1], 16;" :: "r"(dst), "l"(src));
}

// ---------------------------------------------------------------------------
// Bit-pack adjacency (transposed): abT[c*N + i] = bits of adj[i][c*32..+31]
// ---------------------------------------------------------------------------
__global__ void __launch_bounds__(256) adjpack(const int* __restrict__ adj,
                                               uint32_t* __restrict__ abT) {
    const int warp = (blockIdx.x * blockDim.x + threadIdx.x) >> 5;  // row
    const int lane = threadIdx.x & 31;
    if (warp >= N_NODES) return;
    const int* row = adj + (size_t)warp * N_NODES;
    #pragma unroll 4
    for (int c = 0; c < NWORDS; c++) {
        int a = row[c * 32 + lane];
        uint32_t m = __ballot_sync(0xffffffffu, a != 0);
        if (lane == 0) abT[(size_t)c * N_NODES + warp] = m;
    }
}

// ---------------------------------------------------------------------------
// GEMM: Wh = h @ W (fp32 SIMT, ~1 GFLOP)
// ---------------------------------------------------------------------------
__global__ void __launch_bounds__(256) gemm_wh(const float* __restrict__ A,
                                               const float* __restrict__ B,
                                               float* __restrict__ C) {
    __shared__ float As[64 * 16];
    __shared__ float Bs[16 * 64];
    const int t = threadIdx.x;
    const int tx = t & 15;
    const int ty = t >> 4;
    const int i0 = blockIdx.y * 64;
    const int c0 = blockIdx.x * 64;

    float acc[4][4] = {};
    for (int k0 = 0; k0 < DIM; k0 += 16) {
        __syncthreads();
        {
            int e = t * 4;
            int r = e >> 4, kk = e & 15;
            *(float4*)&As[e] = *(const float4*)&A[(size_t)(i0 + r) * DIM + k0 + kk];
        }
        {
            int e = t * 4;
            int kr = e >> 6, cc = e & 63;
            *(float4*)&Bs[e] = *(const float4*)&B[(size_t)(k0 + kr) * DIM + c0 + cc];
        }
        __syncthreads();
        #pragma unroll
        for (int k = 0; k < 16; k++) {
            float a[4];
            #pragma unroll
            for (int m = 0; m < 4; m++) a[m] = As[(ty * 4 + m) * 16 + k];
            float4 bb = *(float4*)&Bs[k * 64 + tx * 4];
            float b[4] = {bb.x, bb.y, bb.z, bb.w};
            #pragma unroll
            for (int m = 0; m < 4; m++)
                #pragma unroll
                for (int n = 0; n < 4; n++)
                    acc[m][n] = fmaf(a[m], b[n], acc[m][n]);
        }
    }
    #pragma unroll
    for (int m = 0; m < 4; m++)
        #pragma unroll
        for (int n = 0; n < 4; n++)
            C[(size_t)(i0 + ty * 4 + m) * DIM + c0 + tx * 4 + n] = acc[m][n];
}

// ---------------------------------------------------------------------------
// Pack V pairs: Vp[(c*16+w)*256+n] = (tf32(Wh[j0][n]), tf32(Wh[j0+4][n]))
//   j0 = c*32 + (w>>2)*8 + (w&3)
// ---------------------------------------------------------------------------
__global__ void __launch_bounds__(256) vpack(const float* __restrict__ Wh,
                                             float2* __restrict__ Vp) {
    const int c = blockIdx.x;
    const int t = threadIdx.x;
    #pragma unroll
    for (int w = 0; w < 16; w++) {
        int j0 = c * 32 + (w >> 2) * 8 + (w & 3);
        float v0 = Wh[(size_t)j0 * DIM + t];
        float v1 = Wh[(size_t)(j0 + 4) * DIM + t];
        Vp[(size_t)(c * 16 + w) * 256 + t] = make_float2(tf32r(v0), tf32r(v1));
    }
}

// ---------------------------------------------------------------------------
// sL_i = (Wh[i,:].a_src)*log2e ; dL_i = (Wh[i,:].a_dst)*log2e
// ---------------------------------------------------------------------------
__global__ void __launch_bounds__(256) compute_sd(const float* __restrict__ Wh,
                                                  const float* __restrict__ a_src,
                                                  const float* __restrict__ a_dst) {
    int warp = (blockIdx.x * blockDim.x + threadIdx.x) >> 5;
    int lane = threadIdx.x & 31;
    if (warp >= N_NODES) return;
    const float* row = Wh + (size_t)warp * DIM;
    float ps = 0.f, pd = 0.f;
    #pragma unroll
    for (int c = lane; c < DIM; c += 32) {
        float v = row[c];
        ps = fmaf(v, a_src[c], ps);
        pd = fmaf(v, a_dst[c], pd);
    }
    #pragma unroll
    for (int o = 16; o > 0; o >>= 1) {
        ps += __shfl_down_sync(0xffffffffu, ps, o);
        pd += __shfl_down_sync(0xffffffffu, pd, o);
    }
    if (lane == 0) { g_sL[warp] = ps * LOG2E; g_dL[warp] = pd * LOG2E; }
}

// ---------------------------------------------------------------------------
// Fused attention * Wh, tf32 mma.sync. P produced ONCE per element into smem
// (R7 pipeline), adjacency via bitmask, softmax unstabilized (range-safe):
// p = 2^(max(t2, 0.2*t2)), t2 = sL_i + dL_j, masked by adj bit.
// BM=64, BN=256, BK=32, split-K=2. 256 thr = 8 warps (2M x 4N),
// warp tile M32 x N64. grid (128, 2), 2 CTAs/SM.
// ---------------------------------------------------------------------------
#define PA_STRIDE 36
#define PA_FLOATS (64 * PA_STRIDE)          // 2304
#define VROW 520                            // 512 data + 8 pad (==8 mod 32)
#define VP_FLOATS (16 * VROW)               // 8320
#define SMEM_FLOATS (2 * PA_FLOATS + 2 * VP_FLOATS)
#define SMEM_BYTES (SMEM_FLOATS * 4 + 16)

__global__ void __launch_bounds__(256, 2) gat_mma(const float2* __restrict__ Vp,
                                                  const uint32_t* __restrict__ abT,
                                                  float* __restrict__ Dp,
                                                  float* __restrict__ Zp) {
    extern __shared__ float smem[];
    float* spA = smem;                      // [2][PA_FLOATS]
    float* svp = smem + 2 * PA_FLOATS;      // [2][VP_FLOATS]

    const int t = threadIdx.x;
    const int lane = t & 31;
    const int warp = t >> 5;
    const int warpM = warp >> 2;            // 0..1
    const int warpN = warp & 3;             // 0..3
    const int gid = lane >> 2;              // 0..7
    const int tig = lane & 3;               // 0..3
    const int i0 = blockIdx.x * BM;
    const int split = blockIdx.y;
    const int ch0 = split * (NCHUNK_TOT / SPLIT);   // chunk base == word base

    Dp += (size_t)split * N_NODES * DIM;
    Zp += (size_t)split * N_NODES;

    // P producer: thread -> row pr (0..63), cols kb..kb+7 (of 32)
    const int pr = t >> 2;
    const int kb = (t & 3) * 8;
    const float sL_r = g_sL[i0 + pr];
    const uint32_t* awcol = abT + i0 + pr;          // + (ch0+it)*N per iter
    const float* dbase = g_dL + split * KSPAN;

    float4 acc[2][8];
    #pragma unroll
    for (int m = 0; m < 2; m++)
        #pragma unroll
        for (int n = 0; n < 8; n++) acc[m][n] = make_float4(0.f, 0.f, 0.f, 0.f);
    float zacc = 0.f;

    const uint32_t sv_u32 = (uint32_t)__cvta_generic_to_shared(svp);

    auto produce_P = [&](float* buf, uint32_t aw, const float4 dv[2]) {
        const float dj[8] = {dv[0].x, dv[0].y, dv[0].z, dv[0].w,
                             dv[1].x, dv[1].y, dv[1].z, dv[1].w};
        float p[8];
        #pragma unroll
        for (int q = 0; q < 8; q++) {
            float t2 = sL_r + dj[q];
            float e = ex2(fmaxf(t2, 0.2f * t2));
            p[q] = ((aw >> (kb + q)) & 1u) ? e : 0.f;
        }
        zacc += ((p[0] + p[1]) + (p[2] + p[3])) + ((p[4] + p[5]) + (p[6] + p[7]));
        float* dst = buf + pr * PA_STRIDE + kb;
        *(float4*)dst = make_float4(tf32r(p[0]), tf32r(p[1]), tf32r(p[2]), tf32r(p[3]));
        *(float4*)(dst + 4) = make_float4(tf32r(p[4]), tf32r(p[5]), tf32r(p[6]), tf32r(p[7]));
    };

    auto issue_V = [&](int buf, int chunk) {
        const char* gsrc = (const char*)(Vp + (size_t)chunk * 16 * 256);
        uint32_t base = sv_u32 + buf * (VP_FLOATS * 4);
        #pragma unroll
        for (int w = 0; w < 8; w++) {
            int qid = t + 256 * w;           // 16B chunk id (0..2047)
            int rp = qid >> 7;
            int off = (qid & 127) * 16;
            cp_async16(base + rp * (VROW * 4) + off, gsrc + qid * 16);
        }
        asm volatile("cp.async.commit_group;" ::: "memory");
    };

    // ---- prologue: chunk 0 into buffer 0 ----
    {
        uint32_t aw = awcol[(size_t)ch0 * N_NODES];
        float4 dv[2];
        dv[0] = *(const float4*)&dbase[0];
        dv[1] = *(const float4*)&dbase[4];
        // NOTE: producer covers cols kb..kb+7; dv must match those cols:
        dv[0] = *(const float4*)&dbase[kb];
        dv[1] = *(const float4*)&dbase[kb + 4];
        produce_P(spA, aw, dv);
        issue_V(0, ch0);
    }

    for (int it = 0; it < NCH; ++it) {
        const int cur = it & 1, nxt = cur ^ 1;
        const bool more = (it + 1 < NCH);

        uint32_t aw = 0;
        float4 dv[2];
        if (more) {
            const int jc = (it + 1) * BK;
            aw = awcol[(size_t)(ch0 + it + 1) * N_NODES];
            dv[0] = *(const float4*)&dbase[jc + kb];
            dv[1] = *(const float4*)&dbase[jc + kb + 4];
        }

        asm volatile("cp.async.wait_group 0;" ::: "memory");
        __syncthreads();   // P[cur] + V[cur] visible; nxt free

        if (more) issue_V(nxt, ch0 + it + 1);

        const float* A = spA + cur * PA_FLOATS;
        const float* Vb = svp + cur * VP_FLOATS;

        #pragma unroll
        for (int kc = 0; kc < 4; kc++) {
            uint32_t a[2][4];
            #pragma unroll
            for (int mt = 0; mt < 2; mt++) {
                const int r = warpM * 32 + mt * 16 + gid;
                const int c = kc * 8 + tig;
                a[mt][0] = __float_as_uint(A[r * PA_STRIDE + c]);
                a[mt][1] = __float_as_uint(A[(r + 8) * PA_STRIDE + c]);
                a[mt][2] = __float_as_uint(A[r * PA_STRIDE + c + 4]);
                a[mt][3] = __float_as_uint(A[(r + 8) * PA_STRIDE + c + 4]);
            }
            const float* vrow = Vb + (kc * 4 + tig) * VROW;
            #pragma unroll
            for (int nt = 0; nt < 8; nt++) {
                const int n = warpN * 64 + nt * 8 + gid;
                float2 b = *(const float2*)&vrow[n * 2];
                uint32_t b0 = __float_as_uint(b.x);
                uint32_t b1 = __float_as_uint(b.y);
                mma_tf32(acc[0][nt], a[0], b0, b1);
                mma_tf32(acc[1][nt], a[1], b0, b1);
            }
        }

        if (more) produce_P(spA + nxt * PA_FLOATS, aw, dv);
    }

    // ---- Z partials (4 producer threads per row -> shfl reduce) ----
    {
        float z = zacc;
        z += __shfl_xor_sync(0xffffffffu, z, 1);
        z += __shfl_xor_sync(0xffffffffu, z, 2);
        if ((t & 3) == 0) Zp[i0 + pr] = z;
    }

    // ---- store partial numerators ----
    #pragma unroll
    for (int mt = 0; mt < 2; mt++) {
        const int r0 = warpM * 32 + mt * 16 + gid;
        const int r1 = r0 + 8;
        #pragma unroll
        for (int nt = 0; nt < 8; nt++) {
            const int col = warpN * 64 + nt * 8 + 2 * tig;
            float4 c = acc[mt][nt];
            *(float2*)&Dp[(size_t)(i0 + r0) * DIM + col] = make_float2(c.x, c.y);
            *(float2*)&Dp[(size_t)(i0 + r1) * DIM + col] = make_float2(c.z, c.w);
        }
    }
}

// ---------------------------------------------------------------------------
// out[i,n] = relu((D0+D1)[i,n] / (Z0+Z1)[i])
// ---------------------------------------------------------------------------
__global__ void __launch_bounds__(256) combine_out(float* __restrict__ out) {
    int idx = blockIdx.x * 256 + threadIdx.x;     // float4 index
    int row = idx >> 6;
    float4 a = ((const float4*)g_Dp[0])[idx];
    float4 b = ((const float4*)g_Dp[1])[idx];
    float z = g_Zp[0][row] + g_Zp[1][row];
    float rz = (z > 0.f) ? 1.f / z : 0.f;
    float4 o;
    o.x = fmaxf((a.x + b.x) * rz, 0.f);
    o.y = fmaxf((a.y + b.y) * rz, 0.f);
    o.z = fmaxf((a.z + b.z) * rz, 0.f);
    o.w = fmaxf((a.w + b.w) * rz, 0.f);
    ((float4*)out)[idx] = o;
}

// ---------------------------------------------------------------------------
static void run_layer(const float* h_in, const float* W,
                      const float* a_src, const float* a_dst, float* out) {
    float *Wh, *Dp, *Zp;
    float2* Vp;
    uint32_t* abT;
    cudaGetSymbolAddress((void**)&Wh, g_Wh);
    cudaGetSymbolAddress((void**)&Vp, g_Vp);
    cudaGetSymbolAddress((void**)&abT, g_abT);
    cudaGetSymbolAddress((void**)&Dp, g_Dp);
    cudaGetSymbolAddress((void**)&Zp, g_Zp);

    gemm_wh<<<dim3(DIM / 64, N_NODES / 64), 256>>>(h_in, W, Wh);
    vpack<<<NCHUNK_TOT, 256>>>(Wh, Vp);
    compute_sd<<<(N_NODES * 32) / 256, 256>>>(Wh, a_src, a_dst);
    gat_mma<<<dim3(N_NODES / BM, SPLIT), 256, SMEM_BYTES>>>(Vp, abT, Dp, Zp);
    combine_out<<<(N_NODES * DIM / 4) / 256, 256>>>(out);
}

extern "C" void kernel_launch(void* const* d_in, const int* in_sizes, int n_in,
                              void* d_out, int out_size) {
    const float* x      = (const float*)d_in[0];
    const int*   adj    = (const int*)d_in[1];
    const float* W1     = (const float*)d_in[2];
    const float* a1_src = (const float*)d_in[3];
    const float* a1_dst = (const float*)d_in[4];
    const float* W2     = (const float*)d_in[5];
    const float* a2_src = (const float*)d_in[6];
    const float* a2_dst = (const float*)d_in[7];
    float* out = (float*)d_out;

    cudaFuncSetAttribute(gat_mma, cudaFuncAttributeMaxDynamicSharedMemorySize,
                         SMEM_BYTES);

    uint32_t* abT;
    cudaGetSymbolAddress((void**)&abT, g_abT);
    adjpack<<<N_NODES / 8, 256>>>(adj, abT);

    float* h1;
    cudaGetSymbolAddress((void**)&h1, g_h1);

    run_layer(x, W1, a1_src, a1_dst, h1);
    run_layer(h1, W2, a2_src, a2_dst, out);
}

// round 10
// speedup vs baseline: 1.7153x; 1.7153x over previous
#include <cuda_runtime.h>
#include <cstdint>

#define N_NODES 8192
#define DIM 256
#define SPLIT 2
#define KSPAN (N_NODES / SPLIT)   // 4096
#define BK 32
#define NCH (KSPAN / BK)          // 128 iters per CTA
#define BM 64
#define NCHUNK_TOT (N_NODES / BK) // 256 packed V chunks
#define LOG2E 1.4426950408889634f

// ---- device scratch (static only) ----
__device__ float  g_Wh[N_NODES * DIM];          // fp32 Wh
__device__ float  g_At[N_NODES * DIM];          // tf32-rounded gemm A operand
__device__ float2 g_Wp[(DIM / BK) * 16 * 256];  // packed tf32 W pairs (256 KB)
__device__ float2 g_Vp[NCHUNK_TOT * 16 * 256];  // packed tf32 V pairs (8 MB)
__device__ float  g_h1[N_NODES * DIM];
__device__ float  g_Dp[SPLIT][N_NODES * DIM];   // split-K partial numerators
__device__ float  g_Zp[SPLIT][N_NODES];         // split-K partial Z
__device__ float  g_sL[N_NODES];                // s * log2(e)
__device__ float  g_dL[N_NODES];                // d * log2(e)

__device__ __forceinline__ float tf32r(float x) {
    uint32_t u;
    asm("cvt.rna.tf32.f32 %0, %1;" : "=r"(u) : "f"(x));
    return __uint_as_float(u);
}
__device__ __forceinline__ float ex2(float x) {
    float r;
    asm("ex2.approx.f32 %0, %1;" : "=f"(r) : "f"(x));
    return r;
}
__device__ __forceinline__ void mma_tf32(float4& c, const uint32_t a[4],
                                         uint32_t b0, uint32_t b1) {
    asm volatile(
        "mma.sync.aligned.m16n8k8.row.col.f32.tf32.tf32.f32 "
        "{%0,%1,%2,%3}, {%4,%5,%6,%7}, {%8,%9}, {%0,%1,%2,%3};"
        : "+f"(c.x), "+f"(c.y), "+f"(c.z), "+f"(c.w)
        : "r"(a[0]), "r"(a[1]), "r"(a[2]), "r"(a[3]), "r"(b0), "r"(b1));
}
__device__ __forceinline__ void cp_async16(uint32_t dst, const void* src) {
    asm volatile("cp.async.cg.shared.global [%0], [%1], 16;" :: "r"(dst), "l"(src));
}

// ---------------------------------------------------------------------------
// apack: tf32-round A operand elementwise
// ---------------------------------------------------------------------------
__global__ void __launch_bounds__(256) apack(const float* __restrict__ A,
                                             float* __restrict__ At) {
    int idx = blockIdx.x * 256 + threadIdx.x;
    float4 v = ((const float4*)A)[idx];
    ((float4*)At)[idx] = make_float4(tf32r(v.x), tf32r(v.y), tf32r(v.z), tf32r(v.w));
}

// ---------------------------------------------------------------------------
// wpack: Wp[(c*16+w)*256+n] = (tf32(W[j0][n]), tf32(W[j0+4][n]))
//   j0 = c*32 + (w>>2)*8 + (w&3), c in 0..7   (W is 256x256)
// ---------------------------------------------------------------------------
__global__ void __launch_bounds__(256) wpack(const float* __restrict__ W,
                                             float2* __restrict__ Wp) {
    const int c = blockIdx.x;
    const int t = threadIdx.x;
    #pragma unroll
    for (int w = 0; w < 16; w++) {
        int j0 = c * 32 + (w >> 2) * 8 + (w & 3);
        float v0 = W[(size_t)j0 * DIM + t];
        float v1 = W[(size_t)(j0 + 4) * DIM + t];
        Wp[(size_t)(c * 16 + w) * 256 + t] = make_float2(tf32r(v0), tf32r(v1));
    }
}

// ---------------------------------------------------------------------------
// Tensor-core GEMM: Wh = At @ W  (A pre-rounded, W pre-packed).
// BM=64, BN=256, BK=32, 8 K-chunks, double-buffered. 256 thr, 8 warps 2Mx4N.
// ---------------------------------------------------------------------------
#define GA_STRIDE 36                        // floats; 144 B row (16B-aligned)
#define GA_FLOATS (64 * GA_STRIDE)          // 2304
#define GVROW 520
#define GW_FLOATS (16 * GVROW)              // 8320
#define GSMEM_BYTES ((2 * GA_FLOATS + 2 * GW_FLOATS) * 4 + 16)

__global__ void __launch_bounds__(256, 2) gemm_tc(const float* __restrict__ At,
                                                  const float2* __restrict__ Wp,
                                                  float* __restrict__ C) {
    extern __shared__ float smem[];
    float* sA = smem;                       // [2][GA_FLOATS]
    float* sW = smem + 2 * GA_FLOATS;       // [2][GW_FLOATS]

    const int t = threadIdx.x;
    const int lane = t & 31;
    const int warp = t >> 5;
    const int warpM = warp >> 2;
    const int warpN = warp & 3;
    const int gid = lane >> 2;
    const int tig = lane & 3;
    const int i0 = blockIdx.x * 64;

    const uint32_t sA_u32 = (uint32_t)__cvta_generic_to_shared(sA);
    const uint32_t sW_u32 = (uint32_t)__cvta_generic_to_shared(sW);

    float4 acc[2][8];
    #pragma unroll
    for (int m = 0; m < 2; m++)
        #pragma unroll
        for (int n = 0; n < 8; n++) acc[m][n] = make_float4(0.f, 0.f, 0.f, 0.f);

    auto stage = [&](int buf, int ch) {
        // A tile: 64 rows x 32 floats = 512 16B units, 2/thread
        #pragma unroll
        for (int w = 0; w < 2; w++) {
            int qid = t + 256 * w;
            int rp = qid >> 3, u = qid & 7;
            cp_async16(sA_u32 + buf * (GA_FLOATS * 4) + rp * (GA_STRIDE * 4) + u * 16,
                       At + (size_t)(i0 + rp) * DIM + ch * 32 + u * 4);
        }
        // W tile: 16 pair-rows x 512 floats = 2048 units, 8/thread
        const char* gsrc = (const char*)(Wp + (size_t)ch * 16 * 256);
        #pragma unroll
        for (int w = 0; w < 8; w++) {
            int qid = t + 256 * w;
            int rp = qid >> 7;
            int off = (qid & 127) * 16;
            cp_async16(sW_u32 + buf * (GW_FLOATS * 4) + rp * (GVROW * 4) + off,
                       gsrc + qid * 16);
        }
        asm volatile("cp.async.commit_group;" ::: "memory");
    };

    stage(0, 0);

    #pragma unroll
    for (int it = 0; it < 8; ++it) {
        const int cur = it & 1, nxt = cur ^ 1;
        asm volatile("cp.async.wait_group 0;" ::: "memory");
        __syncthreads();
        if (it + 1 < 8) stage(nxt, it + 1);

        const float* A = sA + cur * GA_FLOATS;
        const float* Wb = sW + cur * GW_FLOATS;

        #pragma unroll
        for (int kc = 0; kc < 4; kc++) {
            uint32_t a[2][4];
            #pragma unroll
            for (int mt = 0; mt < 2; mt++) {
                const int r = warpM * 32 + mt * 16 + gid;
                const int c = kc * 8 + tig;
                a[mt][0] = __float_as_uint(A[r * GA_STRIDE + c]);
                a[mt][1] = __float_as_uint(A[(r + 8) * GA_STRIDE + c]);
                a[mt][2] = __float_as_uint(A[r * GA_STRIDE + c + 4]);
                a[mt][3] = __float_as_uint(A[(r + 8) * GA_STRIDE + c + 4]);
            }
            const float* vrow = Wb + (kc * 4 + tig) * GVROW;
            #pragma unroll
            for (int nt = 0; nt < 8; nt++) {
                const int n = warpN * 64 + nt * 8 + gid;
                float2 b = *(const float2*)&vrow[n * 2];
                mma_tf32(acc[0][nt], a[0], __float_as_uint(b.x), __float_as_uint(b.y));
                mma_tf32(acc[1][nt], a[1], __float_as_uint(b.x), __float_as_uint(b.y));
            }
        }
        __syncthreads();
    }

    #pragma unroll
    for (int mt = 0; mt < 2; mt++) {
        const int r0 = warpM * 32 + mt * 16 + gid;
        const int r1 = r0 + 8;
        #pragma unroll
        for (int nt = 0; nt < 8; nt++) {
            const int col = warpN * 64 + nt * 8 + 2 * tig;
            float4 c = acc[mt][nt];
            *(float2*)&C[(size_t)(i0 + r0) * DIM + col] = make_float2(c.x, c.y);
            *(float2*)&C[(size_t)(i0 + r1) * DIM + col] = make_float2(c.z, c.w);
        }
    }
}

// ---------------------------------------------------------------------------
// Pack V pairs (from fp32 Wh): Vp[(c*16+w)*256+n] = (tf32(Wh[j0][n]), tf32(Wh[j0+4][n]))
// ---------------------------------------------------------------------------
__global__ void __launch_bounds__(256) vpack(const float* __restrict__ Wh,
                                             float2* __restrict__ Vp) {
    const int c = blockIdx.x;
    const int t = threadIdx.x;
    #pragma unroll
    for (int w = 0; w < 16; w++) {
        int j0 = c * 32 + (w >> 2) * 8 + (w & 3);
        float v0 = Wh[(size_t)j0 * DIM + t];
        float v1 = Wh[(size_t)(j0 + 4) * DIM + t];
        Vp[(size_t)(c * 16 + w) * 256 + t] = make_float2(tf32r(v0), tf32r(v1));
    }
}

// ---------------------------------------------------------------------------
// sL_i = (Wh[i,:].a_src)*log2e ; dL_i = (Wh[i,:].a_dst)*log2e
// ---------------------------------------------------------------------------
__global__ void __launch_bounds__(256) compute_sd(const float* __restrict__ Wh,
                                                  const float* __restrict__ a_src,
                                                  const float* __restrict__ a_dst) {
    int warp = (blockIdx.x * blockDim.x + threadIdx.x) >> 5;
    int lane = threadIdx.x & 31;
    if (warp >= N_NODES) return;
    const float* row = Wh + (size_t)warp * DIM;
    float ps = 0.f, pd = 0.f;
    #pragma unroll
    for (int c = lane; c < DIM; c += 32) {
        float v = row[c];
        ps = fmaf(v, a_src[c], ps);
        pd = fmaf(v, a_dst[c], pd);
    }
    #pragma unroll
    for (int o = 16; o > 0; o >>= 1) {
        ps += __shfl_down_sync(0xffffffffu, ps, o);
        pd += __shfl_down_sync(0xffffffffu, pd, o);
    }
    if (lane == 0) { g_sL[warp] = ps * LOG2E; g_dL[warp] = pd * LOG2E; }
}

// ---------------------------------------------------------------------------
// Fused attention * Wh (EXACT R7 pipeline; int4 adjacency; unstabilized P):
//   p = 2^(max(t2, 0.2*t2)), t2 = sL_i + dL_j  (pre-scaled by log2e)
// BM=64, BN=256, BK=32, split-K=2. 256 thr = 8 warps (2M x 4N), warp tile
// M32 x N64. grid (128, 2), 2 CTAs/SM.
// ---------------------------------------------------------------------------
#define PA_STRIDE 36
#define PA_FLOATS (64 * PA_STRIDE)          // 2304
#define VROW 520                            // 512 data + 8 pad (==8 mod 32)
#define VP_FLOATS (16 * VROW)               // 8320
#define SMEM_FLOATS (2 * PA_FLOATS + 2 * VP_FLOATS)
#define SMEM_BYTES (SMEM_FLOATS * 4 + 16)

__global__ void __launch_bounds__(256, 2) gat_mma(const float2* __restrict__ Vp,
                                                  const int* __restrict__ adj,
                                                  float* __restrict__ Dp,
                                                  float* __restrict__ Zp) {
    extern __shared__ float smem[];
    float* spA = smem;                      // [2][PA_FLOATS]
    float* svp = smem + 2 * PA_FLOATS;      // [2][VP_FLOATS]

    const int t = threadIdx.x;
    const int lane = t & 31;
    const int warp = t >> 5;
    const int warpM = warp >> 2;            // 0..1
    const int warpN = warp & 3;             // 0..3
    const int gid = lane >> 2;              // 0..7
    const int tig = lane & 3;               // 0..3
    const int i0 = blockIdx.x * BM;
    const int split = blockIdx.y;
    const int ch0 = split * (NCHUNK_TOT / SPLIT);

    Dp += (size_t)split * N_NODES * DIM;
    Zp += (size_t)split * N_NODES;

    // P producer: thread -> row pr (0..63), cols kb..kb+7 (of 32)
    const int pr = t >> 2;
    const int kb = (t & 3) * 8;
    const float sL_r = g_sL[i0 + pr];
    const int* adjrow = adj + (size_t)(i0 + pr) * N_NODES + split * KSPAN;
    const float* dbase = g_dL + split * KSPAN;

    float4 acc[2][8];
    #pragma unroll
    for (int m = 0; m < 2; m++)
        #pragma unroll
        for (int n = 0; n < 8; n++) acc[m][n] = make_float4(0.f, 0.f, 0.f, 0.f);
    float zacc = 0.f;

    const uint32_t sv_u32 = (uint32_t)__cvta_generic_to_shared(svp);

    auto produce_P = [&](float* buf, const int4 aj[2], const float4 dv[2]) {
        const float dj[8] = {dv[0].x, dv[0].y, dv[0].z, dv[0].w,
                             dv[1].x, dv[1].y, dv[1].z, dv[1].w};
        const int mk[8] = {aj[0].x, aj[0].y, aj[0].z, aj[0].w,
                           aj[1].x, aj[1].y, aj[1].z, aj[1].w};
        float p[8];
        #pragma unroll
        for (int q = 0; q < 8; q++) {
            float t2 = sL_r + dj[q];
            float e = ex2(fmaxf(t2, 0.2f * t2));
            p[q] = mk[q] ? e : 0.f;
        }
        zacc += ((p[0] + p[1]) + (p[2] + p[3])) + ((p[4] + p[5]) + (p[6] + p[7]));
        float* dst = buf + pr * PA_STRIDE + kb;
        *(float4*)dst = make_float4(tf32r(p[0]), tf32r(p[1]), tf32r(p[2]), tf32r(p[3]));
        *(float4*)(dst + 4) = make_float4(tf32r(p[4]), tf32r(p[5]), tf32r(p[6]), tf32r(p[7]));
    };

    auto issue_V = [&](int buf, int chunk) {
        const char* gsrc = (const char*)(Vp + (size_t)chunk * 16 * 256);
        uint32_t base = sv_u32 + buf * (VP_FLOATS * 4);
        #pragma unroll
        for (int w = 0; w < 8; w++) {
            int qid = t + 256 * w;
            int rp = qid >> 7;
            int off = (qid & 127) * 16;
            cp_async16(base + rp * (VROW * 4) + off, gsrc + qid * 16);
        }
        asm volatile("cp.async.commit_group;" ::: "memory");
    };

    // ---- prologue: chunk 0 into buffer 0 ----
    {
        int4 aj[2]; float4 dv[2];
        aj[0] = *(const int4*)&adjrow[kb];
        aj[1] = *(const int4*)&adjrow[kb + 4];
        dv[0] = *(const float4*)&dbase[kb];
        dv[1] = *(const float4*)&dbase[kb + 4];
        produce_P(spA, aj, dv);
        issue_V(0, ch0);
    }

    for (int it = 0; it < NCH; ++it) {
        const int cur = it & 1, nxt = cur ^ 1;
        const bool more = (it + 1 < NCH);

        int4 aj[2]; float4 dv[2];
        if (more) {
            const int jc = (it + 1) * BK;
            aj[0] = *(const int4*)&adjrow[jc + kb];
            aj[1] = *(const int4*)&adjrow[jc + kb + 4];
            dv[0] = *(const float4*)&dbase[jc + kb];
            dv[1] = *(const float4*)&dbase[jc + kb + 4];
        }

        asm volatile("cp.async.wait_group 0;" ::: "memory");
        __syncthreads();   // P[cur] + V[cur] visible; nxt free

        if (more) issue_V(nxt, ch0 + it + 1);

        const float* A = spA + cur * PA_FLOATS;
        const float* Vb = svp + cur * VP_FLOATS;

        #pragma unroll
        for (int kc = 0; kc < 4; kc++) {
            uint32_t a[2][4];
            #pragma unroll
            for (int mt = 0; mt < 2; mt++) {
                const int r = warpM * 32 + mt * 16 + gid;
                const int c = kc * 8 + tig;
                a[mt][0] = __float_as_uint(A[r * PA_STRIDE + c]);
                a[mt][1] = __float_as_uint(A[(r + 8) * PA_STRIDE + c]);
                a[mt][2] = __float_as_uint(A[r * PA_STRIDE + c + 4]);
                a[mt][3] = __float_as_uint(A[(r + 8) * PA_STRIDE + c + 4]);
            }
            const float* vrow = Vb + (kc * 4 + tig) * VROW;
            #pragma unroll
            for (int nt = 0; nt < 8; nt++) {
                const int n = warpN * 64 + nt * 8 + gid;
                float2 b = *(const float2*)&vrow[n * 2];
                mma_tf32(acc[0][nt], a[0], __float_as_uint(b.x), __float_as_uint(b.y));
                mma_tf32(acc[1][nt], a[1], __float_as_uint(b.x), __float_as_uint(b.y));
            }
        }

        if (more) produce_P(spA + nxt * PA_FLOATS, aj, dv);
    }

    // ---- Z partials ----
    {
        float z = zacc;
        z += __shfl_xor_sync(0xffffffffu, z, 1);
        z += __shfl_xor_sync(0xffffffffu, z, 2);
        if ((t & 3) == 0) Zp[i0 + pr] = z;
    }

    // ---- store partial numerators ----
    #pragma unroll
    for (int mt = 0; mt < 2; mt++) {
        const int r0 = warpM * 32 + mt * 16 + gid;
        const int r1 = r0 + 8;
        #pragma unroll
        for (int nt = 0; nt < 8; nt++) {
            const int col = warpN * 64 + nt * 8 + 2 * tig;
            float4 c = acc[mt][nt];
            *(float2*)&Dp[(size_t)(i0 + r0) * DIM + col] = make_float2(c.x, c.y);
            *(float2*)&Dp[(size_t)(i0 + r1) * DIM + col] = make_float2(c.z, c.w);
        }
    }
}

// ---------------------------------------------------------------------------
// out[i,n] = relu((D0+D1)[i,n] / (Z0+Z1)[i])
// ---------------------------------------------------------------------------
__global__ void __launch_bounds__(256) combine_out(float* __restrict__ out) {
    int idx = blockIdx.x * 256 + threadIdx.x;
    int row = idx >> 6;
    float4 a = ((const float4*)g_Dp[0])[idx];
    float4 b = ((const float4*)g_Dp[1])[idx];
    float z = g_Zp[0][row] + g_Zp[1][row];
    float rz = (z > 0.f) ? 1.f / z : 0.f;
    float4 o;
    o.x = fmaxf((a.x + b.x) * rz, 0.f);
    o.y = fmaxf((a.y + b.y) * rz, 0.f);
    o.z = fmaxf((a.z + b.z) * rz, 0.f);
    o.w = fmaxf((a.w + b.w) * rz, 0.f);
    ((float4*)out)[idx] = o;
}

// ---------------------------------------------------------------------------
static void run_layer(const float* h_in, const int* adj, const float* W,
                      const float* a_src, const float* a_dst, float* out) {
    float *Wh, *At, *Dp, *Zp;
    float2 *Vp, *Wp;
    cudaGetSymbolAddress((void**)&Wh, g_Wh);
    cudaGetSymbolAddress((void**)&At, g_At);
    cudaGetSymbolAddress((void**)&Wp, g_Wp);
    cudaGetSymbolAddress((void**)&Vp, g_Vp);
    cudaGetSymbolAddress((void**)&Dp, g_Dp);
    cudaGetSymbolAddress((void**)&Zp, g_Zp);

    apack<<<(N_NODES * DIM / 4) / 256, 256>>>(h_in, At);
    wpack<<<DIM / BK, 256>>>(W, Wp);
    gemm_tc<<<N_NODES / 64, 256, GSMEM_BYTES>>>(At, Wp, Wh);
    vpack<<<NCHUNK_TOT, 256>>>(Wh, Vp);
    compute_sd<<<(N_NODES * 32) / 256, 256>>>(Wh, a_src, a_dst);
    gat_mma<<<dim3(N_NODES / BM, SPLIT), 256, SMEM_BYTES>>>(Vp, adj, Dp, Zp);
    combine_out<<<(N_NODES * DIM / 4) / 256, 256>>>(out);
}

extern "C" void kernel_launch(void* const* d_in, const int* in_sizes, int n_in,
                              void* d_out, int out_size) {
    const float* x      = (const float*)d_in[0];
    const int*   adj    = (const int*)d_in[1];
    const float* W1     = (const float*)d_in[2];
    const float* a1_src = (const float*)d_in[3];
    const float* a1_dst = (const float*)d_in[4];
    const float* W2     = (const float*)d_in[5];
    const float* a2_src = (const float*)d_in[6];
    const float* a2_dst = (const float*)d_in[7];
    float* out = (float*)d_out;

    cudaFuncSetAttribute(gat_mma, cudaFuncAttributeMaxDynamicSharedMemorySize,
                         SMEM_BYTES);
    cudaFuncSetAttribute(gemm_tc, cudaFuncAttributeMaxDynamicSharedMemorySize,
                         GSMEM_BYTES);

    float* h1;
    cudaGetSymbolAddress((void**)&h1, g_h1);

    run_layer(x, adj, W1, a1_src, a1_dst, h1);
    run_layer(h1, adj, W2, a2_src, a2_dst, out);
}